// round 1
// baseline (speedup 1.0000x reference)
#include <cuda_runtime.h>

#define Bc 4
#define Nc 2048
#define Dc 64

// ---------------- device scratch (no allocations allowed) ----------------
__device__ float  g_nf[Bc * Nc * Dc];      // normalized features
__device__ float4 g_meta[Bc * Nc * 3];     // (ux,uy,uz,c0) (c1,c2,px,py) (pz,label,mask,0)
__device__ float  g_acc[Bc * Nc * 12];     // per-row: spF smF spC smC spP smP Sall Spos P
__device__ float  g_nll[Bc * Nc];
__device__ float  g_partial[Bc * 8];

__device__ __forceinline__ float sqrt_approx(float x) {
    float r; asm("sqrt.approx.f32 %0, %1;" : "=f"(r) : "f"(x)); return r;
}

// ---------------- kernel 1: per-point precompute ----------------
__global__ void k_prep(const float* __restrict__ feat, const float* __restrict__ flow,
                       const float* __restrict__ pts, const int* __restrict__ colors,
                       const int* __restrict__ sam, const unsigned char* __restrict__ mask) {
    int p = blockIdx.x * blockDim.x + threadIdx.x;
    if (p >= Bc * Nc) return;
    const float4* f = (const float4*)(feat + (size_t)p * Dc);
    float4 buf[16];
    float ss = 0.f;
#pragma unroll
    for (int i = 0; i < 16; i++) {
        float4 v = f[i]; buf[i] = v;
        ss += v.x * v.x + v.y * v.y + v.z * v.z + v.w * v.w;
    }
    float inv = __fdividef(1.f, sqrtf(ss) + 1e-7f);
    float4* o = (float4*)(g_nf + (size_t)p * Dc);
#pragma unroll
    for (int i = 0; i < 16; i++) {
        float4 v = buf[i];
        v.x *= inv; v.y *= inv; v.z *= inv; v.w *= inv;
        o[i] = v;
    }
    float fx = flow[p * 3 + 0], fy = flow[p * 3 + 1], fz = flow[p * 3 + 2];
    float fn = sqrtf(fx * fx + fy * fy + fz * fz);
    float fi = __fdividef(1.f, fmaxf(fn, 1e-20f));
    const float ic = 1.f / 255.f;
    float c0 = colors[p * 3 + 0] * ic, c1 = colors[p * 3 + 1] * ic, c2 = colors[p * 3 + 2] * ic;
    float px = pts[p * 3 + 0], py = pts[p * 3 + 1], pz = pts[p * 3 + 2];
    g_meta[p * 3 + 0] = make_float4(fx * fi, fy * fi, fz * fi, c0);
    g_meta[p * 3 + 1] = make_float4(c1, c2, px, py);
    g_meta[p * 3 + 2] = make_float4(pz, (float)sam[p], mask[p] ? 1.f : 0.f, 0.f);
}

// ---------------- pairwise elementwise math ----------------
__device__ __forceinline__ void ew_loss(float fs, float s, float tau, float enf,
                                        float& ap, float& am) {
    float z = 5.f * (s - tau);          // GAMMA = 5
    float t = __expf(z);
    float gp = __fdividef(t, 1.f + t);  // sigmoid(z) = g_plus; g_minus = 1-gp
    float e1 = __expf(fs * gp);         // exp(eta*fs*g_plus), eta=1
    ap += e1;
    am += e1 * enf;                      // exp(-nu*fs*g_minus) = e1*exp(-fs)
}

__device__ __forceinline__ void pair_ew(float fs,
    const float4& ra, const float4& rb, const float4& rc,
    const float4& ca, const float4& cb, const float4& cc,
    float* acc) {
    float mm = rc.z * cc.z;  // mask outer product
    // flow cosine
    float sflow = (ra.x * ca.x + ra.y * ca.y + ra.z * ca.z) * mm;
    // color: 1 - |dc|/sqrt(3)
    float dx = ra.w - ca.w, dy = rb.x - cb.x, dz = rb.y - cb.y;
    float scol = (1.f - sqrt_approx(dx * dx + dy * dy + dz * dz) * 0.5773502691896258f) * mm;
    // proximity: exp(-|dp| / (2*sigma^2)) , 2*0.1^2 = 0.02 -> *50
    float qx = rb.z - cb.z, qy = rb.w - cb.w, qz = rc.x - cc.x;
    float sprox = __expf(-sqrt_approx(qx * qx + qy * qy + qz * qz) * 50.f) * mm;

    float enf = __expf(-fs);
    float ef  = __expf(fs);
    ew_loss(fs, sflow, 0.8f, enf, acc[0], acc[1]);
    ew_loss(fs, scol,  0.7f, enf, acc[2], acc[3]);
    ew_loss(fs, sprox, 0.5f, enf, acc[4], acc[5]);
    acc[6] += ef;                      // S_all for sam denom
    if (rc.y == cc.y) {                // same label -> positive
        acc[7] += ef;                  // S_pos
        acc[8] += 1.f;                 // P count
    }
}

// ---------------- kernel 2: main N^2 pair loop ----------------
// grid (Nc/32, Bc), block 256. Each block owns 32 rows, sweeps all columns in
// 32-wide tiles. Thread (tx,ty) handles rows {ty, ty+16} x cols {tx, tx+16}.
#define SSTR 68   // padded smem row stride (floats): conflict-free LDS.128

__global__ void __launch_bounds__(256) k_pairs() {
    int b = blockIdx.y, rt = blockIdx.x;
    int tid = threadIdx.x, tx = tid & 15, ty = tid >> 4;
    __shared__ float sA[32 * SSTR];
    __shared__ float sB[32 * SSTR];
    __shared__ float4 sMB[96];

    int rowbase = b * Nc + rt * 32;
    {
        const float4* src = (const float4*)(g_nf + (size_t)rowbase * Dc);
#pragma unroll
        for (int j = tid; j < 512; j += 256) {
            float4 v = src[j];
            ((float4*)(sA + (j >> 4) * SSTR))[j & 15] = v;
        }
    }
    int r0 = ty, r1 = ty + 16;
    float4 ra0 = g_meta[(size_t)(rowbase + r0) * 3 + 0];
    float4 rb0 = g_meta[(size_t)(rowbase + r0) * 3 + 1];
    float4 rc0 = g_meta[(size_t)(rowbase + r0) * 3 + 2];
    float4 ra1 = g_meta[(size_t)(rowbase + r1) * 3 + 0];
    float4 rb1 = g_meta[(size_t)(rowbase + r1) * 3 + 1];
    float4 rc1 = g_meta[(size_t)(rowbase + r1) * 3 + 2];

    float acc0[9], acc1[9];
#pragma unroll
    for (int j = 0; j < 9; j++) { acc0[j] = 0.f; acc1[j] = 0.f; }

    for (int ct = 0; ct < Nc / 32; ct++) {
        __syncthreads();
        int colbase = b * Nc + ct * 32;
        {
            const float4* src = (const float4*)(g_nf + (size_t)colbase * Dc);
#pragma unroll
            for (int j = tid; j < 512; j += 256) {
                float4 v = src[j];
                ((float4*)(sB + (j >> 4) * SSTR))[j & 15] = v;
            }
            if (tid < 96) sMB[tid] = g_meta[(size_t)colbase * 3 + tid];
        }
        __syncthreads();

        int c0 = tx, c1 = tx + 16;
        const float4* A0 = (const float4*)(sA + r0 * SSTR);
        const float4* A1 = (const float4*)(sA + r1 * SSTR);
        const float4* B0 = (const float4*)(sB + c0 * SSTR);
        const float4* B1 = (const float4*)(sB + c1 * SSTR);
        float d00 = 0.f, d01 = 0.f, d10 = 0.f, d11 = 0.f;
#pragma unroll
        for (int k = 0; k < 16; k++) {
            float4 a0 = A0[k], a1 = A1[k], b0 = B0[k], b1 = B1[k];
            d00 = fmaf(a0.x, b0.x, d00); d00 = fmaf(a0.y, b0.y, d00);
            d00 = fmaf(a0.z, b0.z, d00); d00 = fmaf(a0.w, b0.w, d00);
            d01 = fmaf(a0.x, b1.x, d01); d01 = fmaf(a0.y, b1.y, d01);
            d01 = fmaf(a0.z, b1.z, d01); d01 = fmaf(a0.w, b1.w, d01);
            d10 = fmaf(a1.x, b0.x, d10); d10 = fmaf(a1.y, b0.y, d10);
            d10 = fmaf(a1.z, b0.z, d10); d10 = fmaf(a1.w, b0.w, d10);
            d11 = fmaf(a1.x, b1.x, d11); d11 = fmaf(a1.y, b1.y, d11);
            d11 = fmaf(a1.z, b1.z, d11); d11 = fmaf(a1.w, b1.w, d11);
        }
        float4 ca0 = sMB[c0 * 3 + 0], cb0 = sMB[c0 * 3 + 1], cc0 = sMB[c0 * 3 + 2];
        float4 ca1 = sMB[c1 * 3 + 0], cb1 = sMB[c1 * 3 + 1], cc1 = sMB[c1 * 3 + 2];
        pair_ew(d00, ra0, rb0, rc0, ca0, cb0, cc0, acc0);
        pair_ew(d01, ra0, rb0, rc0, ca1, cb1, cc1, acc0);
        pair_ew(d10, ra1, rb1, rc1, ca0, cb0, cc0, acc1);
        pair_ew(d11, ra1, rb1, rc1, ca1, cb1, cc1, acc1);
    }

    // reduce each row's partial sums across the 16 tx lanes (within half-warp)
#pragma unroll
    for (int j = 0; j < 9; j++) {
        float v0 = acc0[j], v1 = acc1[j];
#pragma unroll
        for (int o = 8; o >= 1; o >>= 1) {
            v0 += __shfl_xor_sync(0xffffffffu, v0, o);
            v1 += __shfl_xor_sync(0xffffffffu, v1, o);
        }
        if (tx == 0) {
            g_acc[(size_t)(rowbase + r0) * 12 + j] = v0;
            g_acc[(size_t)(rowbase + r1) * 12 + j] = v1;
        }
    }
}

// ---------------- kernel 3: sparse SAM second pass (warp per row) ----------------
__global__ void __launch_bounds__(256) k_sam(const int* __restrict__ sam) {
    int gw = (blockIdx.x * 256 + threadIdx.x) >> 5;   // global row id
    int lane = threadIdx.x & 31;
    int wl = threadIdx.x >> 5;
    __shared__ float4 sf[8][16];
    int b = gw >> 11;
    if (lane < 16) sf[wl][lane] = ((const float4*)(g_nf + (size_t)gw * Dc))[lane];
    __syncwarp();
    float Sneg = g_acc[(size_t)gw * 12 + 6] - g_acc[(size_t)gw * 12 + 7];
    float P    = g_acc[(size_t)gw * 12 + 8];
    int lbl = sam[gw];
    const int* samb = sam + b * Nc;
    float acc = 0.f;
    for (int m = lane; m < Nc; m += 32) {
        if (samb[m] == lbl) {
            const float4* fm = (const float4*)(g_nf + (size_t)(b * Nc + m) * Dc);
            float fs = 0.f;
#pragma unroll
            for (int k = 0; k < 16; k++) {
                float4 x = sf[wl][k]; float4 y = fm[k];
                fs += x.x * y.x + x.y * y.y + x.z * y.z + x.w * y.w;
            }
            acc += __logf(__expf(fs) + Sneg) - fs;  // log(denom) - logits
        }
    }
#pragma unroll
    for (int o = 16; o >= 1; o >>= 1) acc += __shfl_xor_sync(0xffffffffu, acc, o);
    if (lane == 0) g_nll[gw] = acc / fmaxf(P, 1e-6f);
}

// ---------------- kernel 4: per-batch reduction ----------------
__global__ void k_breduce() {
    int b = blockIdx.x, tid = threadIdx.x;
    float s[6] = {0.f, 0.f, 0.f, 0.f, 0.f, 0.f};
    for (int n = tid; n < Nc; n += 256) {
        size_t r = (size_t)b * Nc + n;
        const float* a = g_acc + r * 12;
        float m = g_meta[r * 3 + 2].z;
        s[0] += m * (log1pf(a[0]) + log1pf(a[1]));   // flow
        s[1] += m * (log1pf(a[2]) + log1pf(a[3]));   // color
        s[2] += m * (log1pf(a[4]) + log1pf(a[5]));   // prox
        s[3] += m;                                    // valid point count
        float valid = a[8] > 0.f ? 1.f : 0.f;
        s[4] += g_nll[r] * valid;                    // sam nll
        s[5] += valid;
    }
    __shared__ float red[256];
#pragma unroll
    for (int j = 0; j < 6; j++) {
        red[tid] = s[j];
        __syncthreads();
        for (int o = 128; o >= 1; o >>= 1) {
            if (tid < o) red[tid] += red[tid + o];
            __syncthreads();
        }
        if (tid == 0) g_partial[b * 8 + j] = red[0];
        __syncthreads();
    }
}

// ---------------- kernel 5: scalar combine ----------------
__global__ void k_final(float* __restrict__ out) {
    float tot = 0.f;
    for (int b = 0; b < Bc; b++) {
        const float* p = g_partial + b * 8;
        float V = p[3];
        tot += -(p[0] + p[1] + p[2]) / V + p[4] / fmaxf(p[5], 1e-6f);
    }
    out[0] = tot * (1.f / Bc);
}

// ---------------- launcher ----------------
extern "C" void kernel_launch(void* const* d_in, const int* in_sizes, int n_in,
                              void* d_out, int out_size) {
    const float* feat         = (const float*)d_in[0];
    const float* flow         = (const float*)d_in[1];
    const float* pts          = (const float*)d_in[2];
    const int* colors         = (const int*)d_in[3];
    const int* sam            = (const int*)d_in[4];
    const unsigned char* mask = (const unsigned char*)d_in[5];

    k_prep<<<(Bc * Nc + 127) / 128, 128>>>(feat, flow, pts, colors, sam, mask);
    dim3 grid(Nc / 32, Bc);
    k_pairs<<<grid, 256>>>();
    k_sam<<<Bc * Nc / 8, 256>>>(sam);
    k_breduce<<<Bc, 256>>>();
    k_final<<<1, 1>>>((float*)d_out);
}

// round 2
// speedup vs baseline: 1.0833x; 1.0833x over previous
#include <cuda_runtime.h>

#define Bc 4
#define Nc 2048
#define Dc 64
#define NSLAB 4
#define CPS (Nc / NSLAB)          // columns per slab = 512
#define CTPS (CPS / 32)           // column tiles per slab = 16

// ---------------- device scratch (no allocations allowed) ----------------
__device__ float  g_nf[Bc * Nc * Dc];            // normalized features
__device__ float4 g_meta[Bc * Nc * 3];           // (ux,uy,uz,c0) (c1,c2,px,py) (pz,label,mask,0)
__device__ float  g_accp[NSLAB * Bc * Nc * 9];   // per-slab per-row: spF smF spC smC spP smP Sall Spos P
__device__ float  g_nll[Bc * Nc];

__device__ __forceinline__ float sqrt_approx(float x) {
    float r; asm("sqrt.approx.f32 %0, %1;" : "=f"(r) : "f"(x)); return r;
}

// ---------------- kernel 1: per-point precompute ----------------
__global__ void k_prep(const float* __restrict__ feat, const float* __restrict__ flow,
                       const float* __restrict__ pts, const int* __restrict__ colors,
                       const int* __restrict__ sam, const unsigned char* __restrict__ mask) {
    int p = blockIdx.x * blockDim.x + threadIdx.x;
    if (p >= Bc * Nc) return;
    const float4* f = (const float4*)(feat + (size_t)p * Dc);
    float4 buf[16];
    float ss = 0.f;
#pragma unroll
    for (int i = 0; i < 16; i++) {
        float4 v = f[i]; buf[i] = v;
        ss += v.x * v.x + v.y * v.y + v.z * v.z + v.w * v.w;
    }
    float inv = __fdividef(1.f, sqrtf(ss) + 1e-7f);
    float4* o = (float4*)(g_nf + (size_t)p * Dc);
#pragma unroll
    for (int i = 0; i < 16; i++) {
        float4 v = buf[i];
        v.x *= inv; v.y *= inv; v.z *= inv; v.w *= inv;
        o[i] = v;
    }
    float fx = flow[p * 3 + 0], fy = flow[p * 3 + 1], fz = flow[p * 3 + 2];
    float fn = sqrtf(fx * fx + fy * fy + fz * fz);
    float fi = __fdividef(1.f, fmaxf(fn, 1e-20f));
    const float ic = 1.f / 255.f;
    float c0 = colors[p * 3 + 0] * ic, c1 = colors[p * 3 + 1] * ic, c2 = colors[p * 3 + 2] * ic;
    float px = pts[p * 3 + 0], py = pts[p * 3 + 1], pz = pts[p * 3 + 2];
    g_meta[p * 3 + 0] = make_float4(fx * fi, fy * fi, fz * fi, c0);
    g_meta[p * 3 + 1] = make_float4(c1, c2, px, py);
    g_meta[p * 3 + 2] = make_float4(pz, (float)sam[p], mask[p] ? 1.f : 0.f, 0.f);
}

// ---------------- pairwise elementwise math ----------------
__device__ __forceinline__ void ew_loss(float fs, float s, float tau, float enf,
                                        float& ap, float& am) {
    float z = 5.f * (s - tau);          // GAMMA = 5
    float t = __expf(z);
    float gp = __fdividef(t, 1.f + t);  // sigmoid(z) = g_plus; g_minus = 1-gp
    float e1 = __expf(fs * gp);         // exp(eta*fs*g_plus), eta=1
    ap += e1;
    am += e1 * enf;                      // exp(-nu*fs*g_minus) = e1*exp(-fs)
}

__device__ __forceinline__ void pair_ew(float fs,
    const float4& ra, const float4& rb, const float4& rc,
    const float4& ca, const float4& cb, const float4& cc,
    float* acc) {
    float mm = rc.z * cc.z;  // mask outer product
    // flow cosine
    float sflow = (ra.x * ca.x + ra.y * ca.y + ra.z * ca.z) * mm;
    // color: 1 - |dc|/sqrt(3)
    float dx = ra.w - ca.w, dy = rb.x - cb.x, dz = rb.y - cb.y;
    float scol = (1.f - sqrt_approx(dx * dx + dy * dy + dz * dz) * 0.5773502691896258f) * mm;
    // proximity: exp(-|dp| / (2*sigma^2)) , 2*0.1^2 = 0.02 -> *50
    float qx = rb.z - cb.z, qy = rb.w - cb.w, qz = rc.x - cc.x;
    float sprox = __expf(-sqrt_approx(qx * qx + qy * qy + qz * qz) * 50.f) * mm;

    float enf = __expf(-fs);
    float ef  = __expf(fs);
    ew_loss(fs, sflow, 0.8f, enf, acc[0], acc[1]);
    ew_loss(fs, scol,  0.7f, enf, acc[2], acc[3]);
    ew_loss(fs, sprox, 0.5f, enf, acc[4], acc[5]);
    acc[6] += ef;                      // S_all for sam denom
    if (rc.y == cc.y) {                // same label -> positive
        acc[7] += ef;                  // S_pos
        acc[8] += 1.f;                 // P count
    }
}

// ---------------- kernel 2: main N^2 pair loop (column-sliced into NSLAB) ----------------
// grid (Nc/32, Bc, NSLAB), block 256. Each block owns 32 rows x 512 cols.
#define SSTR 68   // padded smem row stride (floats): conflict-free LDS.128

__global__ void __launch_bounds__(256) k_pairs() {
    int b = blockIdx.y, rt = blockIdx.x, slab = blockIdx.z;
    int tid = threadIdx.x, tx = tid & 15, ty = tid >> 4;
    __shared__ float sA[32 * SSTR];
    __shared__ float sB[32 * SSTR];
    __shared__ float4 sMB[96];

    int rowbase = b * Nc + rt * 32;
    {
        const float4* src = (const float4*)(g_nf + (size_t)rowbase * Dc);
#pragma unroll
        for (int j = tid; j < 512; j += 256) {
            float4 v = src[j];
            ((float4*)(sA + (j >> 4) * SSTR))[j & 15] = v;
        }
    }
    int r0 = ty, r1 = ty + 16;
    float4 ra0 = g_meta[(size_t)(rowbase + r0) * 3 + 0];
    float4 rb0 = g_meta[(size_t)(rowbase + r0) * 3 + 1];
    float4 rc0 = g_meta[(size_t)(rowbase + r0) * 3 + 2];
    float4 ra1 = g_meta[(size_t)(rowbase + r1) * 3 + 0];
    float4 rb1 = g_meta[(size_t)(rowbase + r1) * 3 + 1];
    float4 rc1 = g_meta[(size_t)(rowbase + r1) * 3 + 2];

    float acc0[9], acc1[9];
#pragma unroll
    for (int j = 0; j < 9; j++) { acc0[j] = 0.f; acc1[j] = 0.f; }

    int ct0 = slab * CTPS;
    for (int ct = ct0; ct < ct0 + CTPS; ct++) {
        __syncthreads();
        int colbase = b * Nc + ct * 32;
        {
            const float4* src = (const float4*)(g_nf + (size_t)colbase * Dc);
#pragma unroll
            for (int j = tid; j < 512; j += 256) {
                float4 v = src[j];
                ((float4*)(sB + (j >> 4) * SSTR))[j & 15] = v;
            }
            if (tid < 96) sMB[tid] = g_meta[(size_t)colbase * 3 + tid];
        }
        __syncthreads();

        int c0 = tx, c1 = tx + 16;
        const float4* A0 = (const float4*)(sA + r0 * SSTR);
        const float4* A1 = (const float4*)(sA + r1 * SSTR);
        const float4* B0 = (const float4*)(sB + c0 * SSTR);
        const float4* B1 = (const float4*)(sB + c1 * SSTR);
        float d00 = 0.f, d01 = 0.f, d10 = 0.f, d11 = 0.f;
#pragma unroll
        for (int k = 0; k < 16; k++) {
            float4 a0 = A0[k], a1 = A1[k], b0 = B0[k], b1 = B1[k];
            d00 = fmaf(a0.x, b0.x, d00); d00 = fmaf(a0.y, b0.y, d00);
            d00 = fmaf(a0.z, b0.z, d00); d00 = fmaf(a0.w, b0.w, d00);
            d01 = fmaf(a0.x, b1.x, d01); d01 = fmaf(a0.y, b1.y, d01);
            d01 = fmaf(a0.z, b1.z, d01); d01 = fmaf(a0.w, b1.w, d01);
            d10 = fmaf(a1.x, b0.x, d10); d10 = fmaf(a1.y, b0.y, d10);
            d10 = fmaf(a1.z, b0.z, d10); d10 = fmaf(a1.w, b0.w, d10);
            d11 = fmaf(a1.x, b1.x, d11); d11 = fmaf(a1.y, b1.y, d11);
            d11 = fmaf(a1.z, b1.z, d11); d11 = fmaf(a1.w, b1.w, d11);
        }
        float4 ca0 = sMB[c0 * 3 + 0], cb0 = sMB[c0 * 3 + 1], cc0 = sMB[c0 * 3 + 2];
        float4 ca1 = sMB[c1 * 3 + 0], cb1 = sMB[c1 * 3 + 1], cc1 = sMB[c1 * 3 + 2];
        pair_ew(d00, ra0, rb0, rc0, ca0, cb0, cc0, acc0);
        pair_ew(d01, ra0, rb0, rc0, ca1, cb1, cc1, acc0);
        pair_ew(d10, ra1, rb1, rc1, ca0, cb0, cc0, acc1);
        pair_ew(d11, ra1, rb1, rc1, ca1, cb1, cc1, acc1);
    }

    // reduce each row's partial sums across the 16 tx lanes (within half-warp)
    float* slabbase = g_accp + (size_t)slab * Bc * Nc * 9;
#pragma unroll
    for (int j = 0; j < 9; j++) {
        float v0 = acc0[j], v1 = acc1[j];
#pragma unroll
        for (int o = 8; o >= 1; o >>= 1) {
            v0 += __shfl_xor_sync(0xffffffffu, v0, o);
            v1 += __shfl_xor_sync(0xffffffffu, v1, o);
        }
        if (tx == 0) {
            slabbase[(size_t)(rowbase + r0) * 9 + j] = v0;
            slabbase[(size_t)(rowbase + r1) * 9 + j] = v1;
        }
    }
}

// ---------------- kernel 3: sparse SAM second pass (warp per row) ----------------
__global__ void __launch_bounds__(256) k_sam(const int* __restrict__ sam) {
    int gw = (blockIdx.x * 256 + threadIdx.x) >> 5;   // global row id
    int lane = threadIdx.x & 31;
    int wl = threadIdx.x >> 5;
    __shared__ float4 sf[8][16];
    int b = gw >> 11;
    if (lane < 16) sf[wl][lane] = ((const float4*)(g_nf + (size_t)gw * Dc))[lane];
    __syncwarp();
    float Sall = 0.f, Spos = 0.f, P = 0.f;
#pragma unroll
    for (int s = 0; s < NSLAB; s++) {
        const float* a = g_accp + ((size_t)s * Bc * Nc + gw) * 9;
        Sall += a[6]; Spos += a[7]; P += a[8];
    }
    float Sneg = Sall - Spos;
    int lbl = sam[gw];
    const int* samb = sam + b * Nc;
    float acc = 0.f;
    for (int m = lane; m < Nc; m += 32) {
        if (samb[m] == lbl) {
            const float4* fm = (const float4*)(g_nf + (size_t)(b * Nc + m) * Dc);
            float fs = 0.f;
#pragma unroll
            for (int k = 0; k < 16; k++) {
                float4 x = sf[wl][k]; float4 y = fm[k];
                fs += x.x * y.x + x.y * y.y + x.z * y.z + x.w * y.w;
            }
            acc += __logf(__expf(fs) + Sneg) - fs;  // log(denom) - logits
        }
    }
#pragma unroll
    for (int o = 16; o >= 1; o >>= 1) acc += __shfl_xor_sync(0xffffffffu, acc, o);
    if (lane == 0) g_nll[gw] = acc / fmaxf(P, 1e-6f);
}

// ---------------- kernel 4: fused per-batch reduction + scalar combine ----------------
// single block, 1024 threads: 256 threads per batch (8 warps each, warp-aligned).
__global__ void __launch_bounds__(1024) k_reduce_final(float* __restrict__ out) {
    int tid = threadIdx.x;
    int b = tid >> 8, t = tid & 255;
    float s[6] = {0.f, 0.f, 0.f, 0.f, 0.f, 0.f};
    for (int n = t; n < Nc; n += 256) {
        size_t r = (size_t)b * Nc + n;
        float a[6] = {0.f, 0.f, 0.f, 0.f, 0.f, 0.f};
        float P = 0.f;
#pragma unroll
        for (int sl = 0; sl < NSLAB; sl++) {
            const float* ap = g_accp + ((size_t)sl * Bc * Nc + r) * 9;
#pragma unroll
            for (int j = 0; j < 6; j++) a[j] += ap[j];
            P += ap[8];
        }
        float m = g_meta[r * 3 + 2].z;
        s[0] += m * (log1pf(a[0]) + log1pf(a[1]));   // flow
        s[1] += m * (log1pf(a[2]) + log1pf(a[3]));   // color
        s[2] += m * (log1pf(a[4]) + log1pf(a[5]));   // prox
        s[3] += m;                                    // valid point count
        float valid = P > 0.f ? 1.f : 0.f;
        s[4] += g_nll[r] * valid;                     // sam nll
        s[5] += valid;
    }
    // warp reduction (each warp lies entirely within one batch: 8 warps/batch)
#pragma unroll
    for (int j = 0; j < 6; j++) {
#pragma unroll
        for (int o = 16; o >= 1; o >>= 1) s[j] += __shfl_xor_sync(0xffffffffu, s[j], o);
    }
    __shared__ float wred[32][6];
    int w = tid >> 5, lane = tid & 31;
    if (lane == 0) {
#pragma unroll
        for (int j = 0; j < 6; j++) wred[w][j] = s[j];
    }
    __syncthreads();
    if (tid == 0) {
        float tot = 0.f;
        for (int bb = 0; bb < Bc; bb++) {
            float p[6] = {0.f, 0.f, 0.f, 0.f, 0.f, 0.f};
            for (int ww = bb * 8; ww < bb * 8 + 8; ww++)
#pragma unroll
                for (int j = 0; j < 6; j++) p[j] += wred[ww][j];
            float V = p[3];
            tot += -(p[0] + p[1] + p[2]) / V + p[4] / fmaxf(p[5], 1e-6f);
        }
        out[0] = tot * (1.f / Bc);
    }
}

// ---------------- launcher ----------------
extern "C" void kernel_launch(void* const* d_in, const int* in_sizes, int n_in,
                              void* d_out, int out_size) {
    const float* feat         = (const float*)d_in[0];
    const float* flow         = (const float*)d_in[1];
    const float* pts          = (const float*)d_in[2];
    const int* colors         = (const int*)d_in[3];
    const int* sam            = (const int*)d_in[4];
    const unsigned char* mask = (const unsigned char*)d_in[5];

    k_prep<<<(Bc * Nc + 127) / 128, 128>>>(feat, flow, pts, colors, sam, mask);
    dim3 grid(Nc / 32, Bc, NSLAB);
    k_pairs<<<grid, 256>>>();
    k_sam<<<Bc * Nc / 8, 256>>>(sam);
    k_reduce_final<<<1, 1024>>>((float*)d_out);
}

// round 3
// speedup vs baseline: 1.1548x; 1.0660x over previous
#include <cuda_runtime.h>

#define Bc 4
#define Nc 2048
#define Dc 64
#define NSLAB 4
#define CPS (Nc / NSLAB)          // columns per slab = 512

// ---------------- device scratch (no allocations allowed) ----------------
__device__ float  g_nf[Bc * Nc * Dc];            // normalized features
__device__ float4 g_meta[Bc * Nc * 3];           // (ux,uy,uz,c0) (c1,c2,px,py) (pz,label,mask,0)
__device__ float  g_accp[NSLAB * Bc * Nc * 9];   // per-slab per-row: spF smF spC smC spP smP Sall Spos P
__device__ float4 g_rowloss[Bc * Nc];            // (wloss*m, m, nll*valid, valid)

__device__ __forceinline__ float sqrt_approx(float x) {
    float r; asm("sqrt.approx.f32 %0, %1;" : "=f"(r) : "f"(x)); return r;
}

// ---------------- kernel 1: per-point precompute ----------------
__global__ void k_prep(const float* __restrict__ feat, const float* __restrict__ flow,
                       const float* __restrict__ pts, const int* __restrict__ colors,
                       const int* __restrict__ sam, const unsigned char* __restrict__ mask) {
    int p = blockIdx.x * blockDim.x + threadIdx.x;
    if (p >= Bc * Nc) return;
    const float4* f = (const float4*)(feat + (size_t)p * Dc);
    float4 buf[16];
    float ss = 0.f;
#pragma unroll
    for (int i = 0; i < 16; i++) {
        float4 v = f[i]; buf[i] = v;
        ss += v.x * v.x + v.y * v.y + v.z * v.z + v.w * v.w;
    }
    float inv = __fdividef(1.f, sqrtf(ss) + 1e-7f);
    float4* o = (float4*)(g_nf + (size_t)p * Dc);
#pragma unroll
    for (int i = 0; i < 16; i++) {
        float4 v = buf[i];
        v.x *= inv; v.y *= inv; v.z *= inv; v.w *= inv;
        o[i] = v;
    }
    float fx = flow[p * 3 + 0], fy = flow[p * 3 + 1], fz = flow[p * 3 + 2];
    float fn = sqrtf(fx * fx + fy * fy + fz * fz);
    float fi = __fdividef(1.f, fmaxf(fn, 1e-20f));
    const float ic = 1.f / 255.f;
    float c0 = colors[p * 3 + 0] * ic, c1 = colors[p * 3 + 1] * ic, c2 = colors[p * 3 + 2] * ic;
    float px = pts[p * 3 + 0], py = pts[p * 3 + 1], pz = pts[p * 3 + 2];
    g_meta[p * 3 + 0] = make_float4(fx * fi, fy * fi, fz * fi, c0);
    g_meta[p * 3 + 1] = make_float4(c1, c2, px, py);
    g_meta[p * 3 + 2] = make_float4(pz, (float)sam[p], mask[p] ? 1.f : 0.f, 0.f);
}

// ---------------- pairwise elementwise math ----------------
__device__ __forceinline__ void ew_loss(float fs, float s, float tau, float enf,
                                        float& ap, float& am) {
    float z = 5.f * (s - tau);          // GAMMA = 5
    float t = __expf(z);
    float gp = __fdividef(t, 1.f + t);  // sigmoid(z) = g_plus; g_minus = 1-gp
    float e1 = __expf(fs * gp);         // exp(eta*fs*g_plus), eta=1
    ap += e1;
    am += e1 * enf;                      // exp(-nu*fs*g_minus) = e1*exp(-fs)
}

__device__ __forceinline__ void pair_ew(float fs,
    const float4& ra, const float4& rb, const float4& rc,
    const float4& ca, const float4& cb, const float4& cc,
    float* acc) {
    float mm = rc.z * cc.z;  // mask outer product
    float sflow = (ra.x * ca.x + ra.y * ca.y + ra.z * ca.z) * mm;
    float dx = ra.w - ca.w, dy = rb.x - cb.x, dz = rb.y - cb.y;
    float scol = (1.f - sqrt_approx(dx * dx + dy * dy + dz * dz) * 0.5773502691896258f) * mm;
    float qx = rb.z - cb.z, qy = rb.w - cb.w, qz = rc.x - cc.x;
    float sprox = __expf(-sqrt_approx(qx * qx + qy * qy + qz * qz) * 50.f) * mm;

    float enf = __expf(-fs);
    float ef  = __expf(fs);
    ew_loss(fs, sflow, 0.8f, enf, acc[0], acc[1]);
    ew_loss(fs, scol,  0.7f, enf, acc[2], acc[3]);
    ew_loss(fs, sprox, 0.5f, enf, acc[4], acc[5]);
    acc[6] += ef;                      // S_all for sam denom
    if (rc.y == cc.y) {                // same label -> positive
        acc[7] += ef;                  // S_pos
        acc[8] += 1.f;                 // P count
    }
}

// ---------------- kernel 2: main N^2 pair loop (2x4 register blocking) ----------------
// grid (Nc/32, Bc, NSLAB), block 256. Block: 32 rows x 512 cols, tiles of 64 cols.
// Thread (tx,ty): rows {ty, ty+16} x cols {tx, tx+16, tx+32, tx+48}.
#define SSTR 68   // padded smem row stride (floats)

__global__ void __launch_bounds__(256) k_pairs() {
    int b = blockIdx.y, rt = blockIdx.x, slab = blockIdx.z;
    int tid = threadIdx.x, tx = tid & 15, ty = tid >> 4;
    __shared__ float sA[32 * SSTR];
    __shared__ float sB[64 * SSTR];
    __shared__ float4 sMB[192];

    int rowbase = b * Nc + rt * 32;
    {
        const float4* src = (const float4*)(g_nf + (size_t)rowbase * Dc);
#pragma unroll
        for (int j = tid; j < 512; j += 256) {
            float4 v = src[j];
            ((float4*)(sA + (j >> 4) * SSTR))[j & 15] = v;
        }
    }
    int r0 = ty, r1 = ty + 16;
    float4 ra0 = g_meta[(size_t)(rowbase + r0) * 3 + 0];
    float4 rb0 = g_meta[(size_t)(rowbase + r0) * 3 + 1];
    float4 rc0 = g_meta[(size_t)(rowbase + r0) * 3 + 2];
    float4 ra1 = g_meta[(size_t)(rowbase + r1) * 3 + 0];
    float4 rb1 = g_meta[(size_t)(rowbase + r1) * 3 + 1];
    float4 rc1 = g_meta[(size_t)(rowbase + r1) * 3 + 2];

    float acc0[9], acc1[9];
#pragma unroll
    for (int j = 0; j < 9; j++) { acc0[j] = 0.f; acc1[j] = 0.f; }

    int colslab = b * Nc + slab * CPS;
    for (int ctile = 0; ctile < CPS / 64; ctile++) {
        __syncthreads();
        int colbase = colslab + ctile * 64;
        {
            const float4* src = (const float4*)(g_nf + (size_t)colbase * Dc);
#pragma unroll
            for (int j = tid; j < 1024; j += 256) {
                float4 v = src[j];
                ((float4*)(sB + (j >> 4) * SSTR))[j & 15] = v;
            }
            if (tid < 192) sMB[tid] = g_meta[(size_t)colbase * 3 + tid];
        }
        __syncthreads();

        const float4* A0 = (const float4*)(sA + r0 * SSTR);
        const float4* A1 = (const float4*)(sA + r1 * SSTR);
        const float4* B0 = (const float4*)(sB + tx * SSTR);
        const float4* B1 = (const float4*)(sB + (tx + 16) * SSTR);
        const float4* B2 = (const float4*)(sB + (tx + 32) * SSTR);
        const float4* B3 = (const float4*)(sB + (tx + 48) * SSTR);
        float d00 = 0.f, d01 = 0.f, d02 = 0.f, d03 = 0.f;
        float d10 = 0.f, d11 = 0.f, d12 = 0.f, d13 = 0.f;
#pragma unroll
        for (int k = 0; k < 16; k++) {
            float4 a0 = A0[k], a1 = A1[k];
            float4 v0 = B0[k], v1 = B1[k], v2 = B2[k], v3 = B3[k];
            d00 = fmaf(a0.x, v0.x, d00); d00 = fmaf(a0.y, v0.y, d00);
            d00 = fmaf(a0.z, v0.z, d00); d00 = fmaf(a0.w, v0.w, d00);
            d01 = fmaf(a0.x, v1.x, d01); d01 = fmaf(a0.y, v1.y, d01);
            d01 = fmaf(a0.z, v1.z, d01); d01 = fmaf(a0.w, v1.w, d01);
            d02 = fmaf(a0.x, v2.x, d02); d02 = fmaf(a0.y, v2.y, d02);
            d02 = fmaf(a0.z, v2.z, d02); d02 = fmaf(a0.w, v2.w, d02);
            d03 = fmaf(a0.x, v3.x, d03); d03 = fmaf(a0.y, v3.y, d03);
            d03 = fmaf(a0.z, v3.z, d03); d03 = fmaf(a0.w, v3.w, d03);
            d10 = fmaf(a1.x, v0.x, d10); d10 = fmaf(a1.y, v0.y, d10);
            d10 = fmaf(a1.z, v0.z, d10); d10 = fmaf(a1.w, v0.w, d10);
            d11 = fmaf(a1.x, v1.x, d11); d11 = fmaf(a1.y, v1.y, d11);
            d11 = fmaf(a1.z, v1.z, d11); d11 = fmaf(a1.w, v1.w, d11);
            d12 = fmaf(a1.x, v2.x, d12); d12 = fmaf(a1.y, v2.y, d12);
            d12 = fmaf(a1.z, v2.z, d12); d12 = fmaf(a1.w, v2.w, d12);
            d13 = fmaf(a1.x, v3.x, d13); d13 = fmaf(a1.y, v3.y, d13);
            d13 = fmaf(a1.z, v3.z, d13); d13 = fmaf(a1.w, v3.w, d13);
        }
        float dr0[4] = {d00, d01, d02, d03};
        float dr1[4] = {d10, d11, d12, d13};
#pragma unroll
        for (int j = 0; j < 4; j++) {
            int c = tx + 16 * j;
            float4 ca = sMB[c * 3 + 0], cb = sMB[c * 3 + 1], cc = sMB[c * 3 + 2];
            pair_ew(dr0[j], ra0, rb0, rc0, ca, cb, cc, acc0);
            pair_ew(dr1[j], ra1, rb1, rc1, ca, cb, cc, acc1);
        }
    }

    // reduce each row's partials across the 16 tx lanes
    float* slabbase = g_accp + (size_t)slab * Bc * Nc * 9;
#pragma unroll
    for (int j = 0; j < 9; j++) {
        float v0 = acc0[j], v1 = acc1[j];
#pragma unroll
        for (int o = 8; o >= 1; o >>= 1) {
            v0 += __shfl_xor_sync(0xffffffffu, v0, o);
            v1 += __shfl_xor_sync(0xffffffffu, v1, o);
        }
        if (tx == 0) {
            slabbase[(size_t)(rowbase + r0) * 9 + j] = v0;
            slabbase[(size_t)(rowbase + r1) * 9 + j] = v1;
        }
    }
}

// ---------------- kernel 3: SAM pass + per-row loss finalize (warp per row) ----------------
__global__ void __launch_bounds__(256) k_sam(const int* __restrict__ sam) {
    int wl = threadIdx.x >> 5, lane = threadIdx.x & 31;
    int gw = blockIdx.x * 8 + wl;                 // global row id; 8 rows/block, same batch
    int b = (blockIdx.x * 8) >> 11;
    __shared__ int slabels[Nc];
    __shared__ float4 sf[8][16];
    const int* samb = sam + b * Nc;
    for (int i = threadIdx.x; i < Nc; i += 256) slabels[i] = samb[i];
    if (lane < 16) sf[wl][lane] = ((const float4*)(g_nf + (size_t)gw * Dc))[lane];
    __syncthreads();

    // sum slab accumulators: lane j (j<9) holds a[j]
    float aj = 0.f;
    if (lane < 9) {
#pragma unroll
        for (int s = 0; s < NSLAB; s++)
            aj += g_accp[((size_t)s * Bc * Nc + gw) * 9 + lane];
    }
    float a0 = __shfl_sync(0xffffffffu, aj, 0);
    float a1 = __shfl_sync(0xffffffffu, aj, 1);
    float a2 = __shfl_sync(0xffffffffu, aj, 2);
    float a3 = __shfl_sync(0xffffffffu, aj, 3);
    float a4 = __shfl_sync(0xffffffffu, aj, 4);
    float a5 = __shfl_sync(0xffffffffu, aj, 5);
    float Sall = __shfl_sync(0xffffffffu, aj, 6);
    float Spos = __shfl_sync(0xffffffffu, aj, 7);
    float P    = __shfl_sync(0xffffffffu, aj, 8);
    float Sneg = Sall - Spos;

    int lbl = slabels[gw - b * Nc];
    float acc = 0.f;
    for (int m = lane; m < Nc; m += 32) {
        if (slabels[m] == lbl) {
            const float4* fm = (const float4*)(g_nf + (size_t)(b * Nc + m) * Dc);
            float fs = 0.f;
#pragma unroll
            for (int k = 0; k < 16; k++) {
                float4 x = sf[wl][k]; float4 y = fm[k];
                fs += x.x * y.x + x.y * y.y + x.z * y.z + x.w * y.w;
            }
            acc += __logf(__expf(fs) + Sneg) - fs;  // log(denom) - logits
        }
    }
#pragma unroll
    for (int o = 16; o >= 1; o >>= 1) acc += __shfl_xor_sync(0xffffffffu, acc, o);

    if (lane == 0) {
        float m = g_meta[(size_t)gw * 3 + 2].z;
        float wloss = m * (log1pf(a0) + log1pf(a1) + log1pf(a2) +
                           log1pf(a3) + log1pf(a4) + log1pf(a5));
        float valid = P > 0.f ? 1.f : 0.f;
        float nll = acc / fmaxf(P, 1e-6f);
        g_rowloss[gw] = make_float4(wloss, m, nll * valid, valid);
    }
}

// ---------------- kernel 4: tiny final reduction ----------------
// single block, 1024 threads: 256 threads per batch (warps batch-aligned).
__global__ void __launch_bounds__(1024) k_final(float* __restrict__ out) {
    int tid = threadIdx.x;
    int b = tid >> 8, t = tid & 255;
    float s0 = 0.f, s1 = 0.f, s2 = 0.f, s3 = 0.f;
    for (int n = t; n < Nc; n += 256) {
        float4 v = g_rowloss[(size_t)b * Nc + n];
        s0 += v.x; s1 += v.y; s2 += v.z; s3 += v.w;
    }
#pragma unroll
    for (int o = 16; o >= 1; o >>= 1) {
        s0 += __shfl_xor_sync(0xffffffffu, s0, o);
        s1 += __shfl_xor_sync(0xffffffffu, s1, o);
        s2 += __shfl_xor_sync(0xffffffffu, s2, o);
        s3 += __shfl_xor_sync(0xffffffffu, s3, o);
    }
    __shared__ float4 wred[32];
    int w = tid >> 5, lane = tid & 31;
    if (lane == 0) wred[w] = make_float4(s0, s1, s2, s3);
    __syncthreads();
    if (tid == 0) {
        float tot = 0.f;
        for (int bb = 0; bb < Bc; bb++) {
            float p0 = 0.f, p1 = 0.f, p2 = 0.f, p3 = 0.f;
            for (int ww = bb * 8; ww < bb * 8 + 8; ww++) {
                float4 v = wred[ww];
                p0 += v.x; p1 += v.y; p2 += v.z; p3 += v.w;
            }
            tot += -p0 / p1 + p2 / fmaxf(p3, 1e-6f);
        }
        out[0] = tot * (1.f / Bc);
    }
}

// ---------------- launcher ----------------
extern "C" void kernel_launch(void* const* d_in, const int* in_sizes, int n_in,
                              void* d_out, int out_size) {
    const float* feat         = (const float*)d_in[0];
    const float* flow         = (const float*)d_in[1];
    const float* pts          = (const float*)d_in[2];
    const int* colors         = (const int*)d_in[3];
    const int* sam            = (const int*)d_in[4];
    const unsigned char* mask = (const unsigned char*)d_in[5];

    k_prep<<<(Bc * Nc + 127) / 128, 128>>>(feat, flow, pts, colors, sam, mask);
    dim3 grid(Nc / 32, Bc, NSLAB);
    k_pairs<<<grid, 256>>>();
    k_sam<<<Bc * Nc / 8, 256>>>(sam);
    k_final<<<1, 1024>>>((float*)d_out);
}

// round 4
// speedup vs baseline: 1.1623x; 1.0065x over previous
#include <cuda_runtime.h>

#define Bc 4
#define Nc 2048
#define Dc 64
#define NSLAB 8
#define CPS (Nc / NSLAB)          // columns per slab = 256

// ---------------- device scratch (no allocations allowed) ----------------
__device__ float  g_nf[Bc * Nc * Dc];            // normalized features
__device__ float4 g_meta[Bc * Nc * 3];           // (ux,uy,uz,c0) (c1,c2,px,py) (pz,label,mask,0)
__device__ float  g_accp[NSLAB * Bc * Nc * 9];   // per-slab per-row partials
__device__ float4 g_blockloss[Bc * Nc / 8];      // per-k_sam-block (wloss,m,nll,valid) sums

__device__ __forceinline__ float sqrt_approx(float x) {
    float r; asm("sqrt.approx.f32 %0, %1;" : "=f"(r) : "f"(x)); return r;
}
__device__ __forceinline__ float ex2_approx(float x) {
    float r; asm("ex2.approx.f32 %0, %1;" : "=f"(r) : "f"(x)); return r;
}
__device__ __forceinline__ float rcp_approx(float x) {
    float r; asm("rcp.approx.f32 %0, %1;" : "=f"(r) : "f"(x)); return r;
}
__device__ __forceinline__ float tanh_approx(float x) {
    float r; asm("tanh.approx.f32 %0, %1;" : "=f"(r) : "f"(x)); return r;
}
#define L2E 1.4426950408889634f

// ---------------- kernel 1: per-point precompute ----------------
__global__ void k_prep(const float* __restrict__ feat, const float* __restrict__ flow,
                       const float* __restrict__ pts, const int* __restrict__ colors,
                       const int* __restrict__ sam, const unsigned char* __restrict__ mask) {
    int p = blockIdx.x * blockDim.x + threadIdx.x;
    if (p >= Bc * Nc) return;
    const float4* f = (const float4*)(feat + (size_t)p * Dc);
    float4 buf[16];
    float ss = 0.f;
#pragma unroll
    for (int i = 0; i < 16; i++) {
        float4 v = f[i]; buf[i] = v;
        ss += v.x * v.x + v.y * v.y + v.z * v.z + v.w * v.w;
    }
    float inv = __fdividef(1.f, sqrtf(ss) + 1e-7f);
    float4* o = (float4*)(g_nf + (size_t)p * Dc);
#pragma unroll
    for (int i = 0; i < 16; i++) {
        float4 v = buf[i];
        v.x *= inv; v.y *= inv; v.z *= inv; v.w *= inv;
        o[i] = v;
    }
    float fx = flow[p * 3 + 0], fy = flow[p * 3 + 1], fz = flow[p * 3 + 2];
    float fn = sqrtf(fx * fx + fy * fy + fz * fz);
    float fi = __fdividef(1.f, fmaxf(fn, 1e-20f));
    const float ic = 1.f / 255.f;
    float c0 = colors[p * 3 + 0] * ic, c1 = colors[p * 3 + 1] * ic, c2 = colors[p * 3 + 2] * ic;
    float px = pts[p * 3 + 0], py = pts[p * 3 + 1], pz = pts[p * 3 + 2];
    g_meta[p * 3 + 0] = make_float4(fx * fi, fy * fi, fz * fi, c0);
    g_meta[p * 3 + 1] = make_float4(c1, c2, px, py);
    g_meta[p * 3 + 2] = make_float4(pz, (float)sam[p], mask[p] ? 1.f : 0.f, 0.f);
}

// ---------------- pairwise elementwise math ----------------
// gp = sigmoid(5(s-tau)) = 0.5 + 0.5*tanh(2.5*(s-tau))   (1 MUFU instead of 2)
// exp(fs*gp)   = ex2(fsl*gp)            with fsl = fs*log2e
// exp(-fs*gm)  = ex2(fsl*gp) * ex2(-fsl)
__device__ __forceinline__ void ew_loss(float fsl, float s, float tau, float enf,
                                        float& ap, float& am) {
    float th = tanh_approx(2.5f * (s - tau));
    float gp = fmaf(0.5f, th, 0.5f);
    float e1 = ex2_approx(fsl * gp);
    ap += e1;
    am += e1 * enf;
}

__device__ __forceinline__ void pair_ew(float fs,
    const float4& ra, const float4& rb, const float4& rc,
    const float4& ca, const float4& cb, const float4& cc,
    float* acc) {
    float mm = rc.z * cc.z;  // mask outer product
    float sflow = (ra.x * ca.x + ra.y * ca.y + ra.z * ca.z) * mm;
    float dx = ra.w - ca.w, dy = rb.x - cb.x, dz = rb.y - cb.y;
    float scol = (1.f - sqrt_approx(dx * dx + dy * dy + dz * dz) * 0.5773502691896258f) * mm;
    float qx = rb.z - cb.z, qy = rb.w - cb.w, qz = rc.x - cc.x;
    // exp(-50*d) = ex2(-50*log2e*d)
    float sprox = ex2_approx(sqrt_approx(qx * qx + qy * qy + qz * qz) * (-50.f * L2E)) * mm;

    float fsl = fs * L2E;
    float enf = ex2_approx(-fsl);        // exp(-fs)
    float ef  = rcp_approx(enf);         // exp(+fs)
    ew_loss(fsl, sflow, 0.8f, enf, acc[0], acc[1]);
    ew_loss(fsl, scol,  0.7f, enf, acc[2], acc[3]);
    ew_loss(fsl, sprox, 0.5f, enf, acc[4], acc[5]);
    acc[6] += ef;                      // S_all for sam denom
    if (rc.y == cc.y) {                // same label -> positive
        acc[7] += ef;                  // S_pos
        acc[8] += 1.f;                 // P count
    }
}

// ---------------- kernel 2: main N^2 pair loop (2x4 register blocking) ----------------
// grid (Nc/32, Bc, NSLAB), block 256. Block: 32 rows x 256 cols, tiles of 64 cols.
#define SSTR 68   // padded smem row stride (floats)

__global__ void __launch_bounds__(256) k_pairs() {
    int b = blockIdx.y, rt = blockIdx.x, slab = blockIdx.z;
    int tid = threadIdx.x, tx = tid & 15, ty = tid >> 4;
    __shared__ float sA[32 * SSTR];
    __shared__ float sB[64 * SSTR];
    __shared__ float4 sMB[192];

    int rowbase = b * Nc + rt * 32;
    {
        const float4* src = (const float4*)(g_nf + (size_t)rowbase * Dc);
#pragma unroll
        for (int j = tid; j < 512; j += 256) {
            float4 v = src[j];
            ((float4*)(sA + (j >> 4) * SSTR))[j & 15] = v;
        }
    }
    int r0 = ty, r1 = ty + 16;
    float4 ra0 = g_meta[(size_t)(rowbase + r0) * 3 + 0];
    float4 rb0 = g_meta[(size_t)(rowbase + r0) * 3 + 1];
    float4 rc0 = g_meta[(size_t)(rowbase + r0) * 3 + 2];
    float4 ra1 = g_meta[(size_t)(rowbase + r1) * 3 + 0];
    float4 rb1 = g_meta[(size_t)(rowbase + r1) * 3 + 1];
    float4 rc1 = g_meta[(size_t)(rowbase + r1) * 3 + 2];

    float acc0[9], acc1[9];
#pragma unroll
    for (int j = 0; j < 9; j++) { acc0[j] = 0.f; acc1[j] = 0.f; }

    int colslab = b * Nc + slab * CPS;
    for (int ctile = 0; ctile < CPS / 64; ctile++) {
        __syncthreads();
        int colbase = colslab + ctile * 64;
        {
            const float4* src = (const float4*)(g_nf + (size_t)colbase * Dc);
#pragma unroll
            for (int j = tid; j < 1024; j += 256) {
                float4 v = src[j];
                ((float4*)(sB + (j >> 4) * SSTR))[j & 15] = v;
            }
            if (tid < 192) sMB[tid] = g_meta[(size_t)colbase * 3 + tid];
        }
        __syncthreads();

        const float4* A0 = (const float4*)(sA + r0 * SSTR);
        const float4* A1 = (const float4*)(sA + r1 * SSTR);
        const float4* B0 = (const float4*)(sB + tx * SSTR);
        const float4* B1 = (const float4*)(sB + (tx + 16) * SSTR);
        const float4* B2 = (const float4*)(sB + (tx + 32) * SSTR);
        const float4* B3 = (const float4*)(sB + (tx + 48) * SSTR);
        float d00 = 0.f, d01 = 0.f, d02 = 0.f, d03 = 0.f;
        float d10 = 0.f, d11 = 0.f, d12 = 0.f, d13 = 0.f;
#pragma unroll
        for (int k = 0; k < 16; k++) {
            float4 a0 = A0[k], a1 = A1[k];
            float4 v0 = B0[k], v1 = B1[k], v2 = B2[k], v3 = B3[k];
            d00 = fmaf(a0.x, v0.x, d00); d00 = fmaf(a0.y, v0.y, d00);
            d00 = fmaf(a0.z, v0.z, d00); d00 = fmaf(a0.w, v0.w, d00);
            d01 = fmaf(a0.x, v1.x, d01); d01 = fmaf(a0.y, v1.y, d01);
            d01 = fmaf(a0.z, v1.z, d01); d01 = fmaf(a0.w, v1.w, d01);
            d02 = fmaf(a0.x, v2.x, d02); d02 = fmaf(a0.y, v2.y, d02);
            d02 = fmaf(a0.z, v2.z, d02); d02 = fmaf(a0.w, v2.w, d02);
            d03 = fmaf(a0.x, v3.x, d03); d03 = fmaf(a0.y, v3.y, d03);
            d03 = fmaf(a0.z, v3.z, d03); d03 = fmaf(a0.w, v3.w, d03);
            d10 = fmaf(a1.x, v0.x, d10); d10 = fmaf(a1.y, v0.y, d10);
            d10 = fmaf(a1.z, v0.z, d10); d10 = fmaf(a1.w, v0.w, d10);
            d11 = fmaf(a1.x, v1.x, d11); d11 = fmaf(a1.y, v1.y, d11);
            d11 = fmaf(a1.z, v1.z, d11); d11 = fmaf(a1.w, v1.w, d11);
            d12 = fmaf(a1.x, v2.x, d12); d12 = fmaf(a1.y, v2.y, d12);
            d12 = fmaf(a1.z, v2.z, d12); d12 = fmaf(a1.w, v2.w, d12);
            d13 = fmaf(a1.x, v3.x, d13); d13 = fmaf(a1.y, v3.y, d13);
            d13 = fmaf(a1.z, v3.z, d13); d13 = fmaf(a1.w, v3.w, d13);
        }
        float dr0[4] = {d00, d01, d02, d03};
        float dr1[4] = {d10, d11, d12, d13};
#pragma unroll
        for (int j = 0; j < 4; j++) {
            int c = tx + 16 * j;
            float4 ca = sMB[c * 3 + 0], cb = sMB[c * 3 + 1], cc = sMB[c * 3 + 2];
            pair_ew(dr0[j], ra0, rb0, rc0, ca, cb, cc, acc0);
            pair_ew(dr1[j], ra1, rb1, rc1, ca, cb, cc, acc1);
        }
    }

    // reduce each row's partials across the 16 tx lanes
    float* slabbase = g_accp + (size_t)slab * Bc * Nc * 9;
#pragma unroll
    for (int j = 0; j < 9; j++) {
        float v0 = acc0[j], v1 = acc1[j];
#pragma unroll
        for (int o = 8; o >= 1; o >>= 1) {
            v0 += __shfl_xor_sync(0xffffffffu, v0, o);
            v1 += __shfl_xor_sync(0xffffffffu, v1, o);
        }
        if (tx == 0) {
            slabbase[(size_t)(rowbase + r0) * 9 + j] = v0;
            slabbase[(size_t)(rowbase + r1) * 9 + j] = v1;
        }
    }
}

// ---------------- kernel 3: SAM pass + per-row loss finalize (warp per row) ----------------
__global__ void __launch_bounds__(256) k_sam(const int* __restrict__ sam) {
    int wl = threadIdx.x >> 5, lane = threadIdx.x & 31;
    int gw = blockIdx.x * 8 + wl;                 // global row id; 8 rows/block, same batch
    int b = (blockIdx.x * 8) >> 11;
    __shared__ int slabels[Nc];
    __shared__ float4 sf[8][16];
    __shared__ float4 srow[8];
    const int* samb = sam + b * Nc;
    for (int i = threadIdx.x; i < Nc; i += 256) slabels[i] = samb[i];
    if (lane < 16) sf[wl][lane] = ((const float4*)(g_nf + (size_t)gw * Dc))[lane];
    __syncthreads();

    // sum slab accumulators: lane j (j<9) holds a[j]
    float aj = 0.f;
    if (lane < 9) {
#pragma unroll
        for (int s = 0; s < NSLAB; s++)
            aj += g_accp[((size_t)s * Bc * Nc + gw) * 9 + lane];
    }
    float a0 = __shfl_sync(0xffffffffu, aj, 0);
    float a1 = __shfl_sync(0xffffffffu, aj, 1);
    float a2 = __shfl_sync(0xffffffffu, aj, 2);
    float a3 = __shfl_sync(0xffffffffu, aj, 3);
    float a4 = __shfl_sync(0xffffffffu, aj, 4);
    float a5 = __shfl_sync(0xffffffffu, aj, 5);
    float Sall = __shfl_sync(0xffffffffu, aj, 6);
    float Spos = __shfl_sync(0xffffffffu, aj, 7);
    float P    = __shfl_sync(0xffffffffu, aj, 8);
    float Sneg = Sall - Spos;

    int lbl = slabels[gw - b * Nc];
    float acc = 0.f;
    for (int m = lane; m < Nc; m += 32) {
        if (slabels[m] == lbl) {
            const float4* fm = (const float4*)(g_nf + (size_t)(b * Nc + m) * Dc);
            float fs = 0.f;
#pragma unroll
            for (int k = 0; k < 16; k++) {
                float4 x = sf[wl][k]; float4 y = fm[k];
                fs += x.x * y.x + x.y * y.y + x.z * y.z + x.w * y.w;
            }
            acc += __logf(__expf(fs) + Sneg) - fs;  // log(denom) - logits
        }
    }
#pragma unroll
    for (int o = 16; o >= 1; o >>= 1) acc += __shfl_xor_sync(0xffffffffu, acc, o);

    if (lane == 0) {
        float m = g_meta[(size_t)gw * 3 + 2].z;
        float wloss = m * (log1pf(a0) + log1pf(a1) + log1pf(a2) +
                           log1pf(a3) + log1pf(a4) + log1pf(a5));
        float valid = P > 0.f ? 1.f : 0.f;
        float nll = acc / fmaxf(P, 1e-6f);
        srow[wl] = make_float4(wloss, m, nll * valid, valid);
    }
    __syncthreads();
    // block-level sum of the 8 row results
    if (threadIdx.x == 0) {
        float4 s = srow[0];
#pragma unroll
        for (int j = 1; j < 8; j++) {
            float4 v = srow[j];
            s.x += v.x; s.y += v.y; s.z += v.z; s.w += v.w;
        }
        g_blockloss[blockIdx.x] = s;
    }
}

// ---------------- kernel 4: tiny final reduction (1024 entries) ----------------
// single block, 1024 threads; entry e belongs to batch e>>8; warps batch-aligned.
__global__ void __launch_bounds__(1024) k_final(float* __restrict__ out) {
    int tid = threadIdx.x;
    float4 v = g_blockloss[tid];
    float s0 = v.x, s1 = v.y, s2 = v.z, s3 = v.w;
#pragma unroll
    for (int o = 16; o >= 1; o >>= 1) {
        s0 += __shfl_xor_sync(0xffffffffu, s0, o);
        s1 += __shfl_xor_sync(0xffffffffu, s1, o);
        s2 += __shfl_xor_sync(0xffffffffu, s2, o);
        s3 += __shfl_xor_sync(0xffffffffu, s3, o);
    }
    __shared__ float4 wred[32];
    int w = tid >> 5, lane = tid & 31;
    if (lane == 0) wred[w] = make_float4(s0, s1, s2, s3);
    __syncthreads();
    if (tid == 0) {
        float tot = 0.f;
        for (int bb = 0; bb < Bc; bb++) {
            float p0 = 0.f, p1 = 0.f, p2 = 0.f, p3 = 0.f;
            for (int ww = bb * 8; ww < bb * 8 + 8; ww++) {
                float4 t = wred[ww];
                p0 += t.x; p1 += t.y; p2 += t.z; p3 += t.w;
            }
            tot += -p0 / p1 + p2 / fmaxf(p3, 1e-6f);
        }
        out[0] = tot * (1.f / Bc);
    }
}

// ---------------- launcher ----------------
extern "C" void kernel_launch(void* const* d_in, const int* in_sizes, int n_in,
                              void* d_out, int out_size) {
    const float* feat         = (const float*)d_in[0];
    const float* flow         = (const float*)d_in[1];
    const float* pts          = (const float*)d_in[2];
    const int* colors         = (const int*)d_in[3];
    const int* sam            = (const int*)d_in[4];
    const unsigned char* mask = (const unsigned char*)d_in[5];

    k_prep<<<(Bc * Nc + 127) / 128, 128>>>(feat, flow, pts, colors, sam, mask);
    dim3 grid(Nc / 32, Bc, NSLAB);
    k_pairs<<<grid, 256>>>();
    k_sam<<<Bc * Nc / 8, 256>>>(sam);
    k_final<<<1, 1024>>>((float*)d_out);
}

// round 5
// speedup vs baseline: 1.3131x; 1.1297x over previous
#include <cuda_runtime.h>

#define Bc 4
#define Nc 2048
#define Dc 64
#define NSLAB 16
#define CPS (Nc / NSLAB)          // columns per slab = 128

// ---------------- device scratch (no allocations allowed) ----------------
__device__ float  g_nf[Bc * Nc * Dc];            // normalized features
__device__ float4 g_meta[Bc * Nc * 3];           // (ux,uy,uz,c0) (c1,c2,px,py) (pz,label,mask,0)
__device__ float  g_accp[NSLAB * Bc * Nc * 9];   // per-slab per-row partials
__device__ float4 g_blockloss[Bc * Nc / 8];      // per-k_sam-block (wloss,m,nll,valid) sums

__device__ __forceinline__ float sqrt_approx(float x) {
    float r; asm("sqrt.approx.f32 %0, %1;" : "=f"(r) : "f"(x)); return r;
}
__device__ __forceinline__ float ex2_approx(float x) {
    float r; asm("ex2.approx.f32 %0, %1;" : "=f"(r) : "f"(x)); return r;
}
__device__ __forceinline__ float rcp_approx(float x) {
    float r; asm("rcp.approx.f32 %0, %1;" : "=f"(r) : "f"(x)); return r;
}
__device__ __forceinline__ float tanh_approx(float x) {
    float r; asm("tanh.approx.f32 %0, %1;" : "=f"(r) : "f"(x)); return r;
}
// packed f32x2 fma: d += a*b (elementwise on both lanes)
__device__ __forceinline__ void fma2(unsigned long long& d, unsigned long long a,
                                     unsigned long long b) {
    asm("fma.rn.f32x2 %0, %1, %2, %0;" : "+l"(d) : "l"(a), "l"(b));
}
__device__ __forceinline__ unsigned long long pk(float x, float y) {
    unsigned long long r; asm("mov.b64 %0, {%1,%2};" : "=l"(r) : "f"(x), "f"(y)); return r;
}
__device__ __forceinline__ float2 upk(unsigned long long v) {
    float2 r; asm("mov.b64 {%0,%1}, %2;" : "=f"(r.x), "=f"(r.y) : "l"(v)); return r;
}
#define L2E 1.4426950408889634f

// ---------------- kernel 1: per-point precompute ----------------
__global__ void k_prep(const float* __restrict__ feat, const float* __restrict__ flow,
                       const float* __restrict__ pts, const int* __restrict__ colors,
                       const int* __restrict__ sam, const unsigned char* __restrict__ mask) {
    int p = blockIdx.x * blockDim.x + threadIdx.x;
    if (p >= Bc * Nc) return;
    const float4* f = (const float4*)(feat + (size_t)p * Dc);
    float4 buf[16];
    float ss = 0.f;
#pragma unroll
    for (int i = 0; i < 16; i++) {
        float4 v = f[i]; buf[i] = v;
        ss += v.x * v.x + v.y * v.y + v.z * v.z + v.w * v.w;
    }
    float inv = __fdividef(1.f, sqrtf(ss) + 1e-7f);
    float4* o = (float4*)(g_nf + (size_t)p * Dc);
#pragma unroll
    for (int i = 0; i < 16; i++) {
        float4 v = buf[i];
        v.x *= inv; v.y *= inv; v.z *= inv; v.w *= inv;
        o[i] = v;
    }
    float fx = flow[p * 3 + 0], fy = flow[p * 3 + 1], fz = flow[p * 3 + 2];
    float fn = sqrtf(fx * fx + fy * fy + fz * fz);
    float fi = __fdividef(1.f, fmaxf(fn, 1e-20f));
    const float ic = 1.f / 255.f;
    float c0 = colors[p * 3 + 0] * ic, c1 = colors[p * 3 + 1] * ic, c2 = colors[p * 3 + 2] * ic;
    float px = pts[p * 3 + 0], py = pts[p * 3 + 1], pz = pts[p * 3 + 2];
    g_meta[p * 3 + 0] = make_float4(fx * fi, fy * fi, fz * fi, c0);
    g_meta[p * 3 + 1] = make_float4(c1, c2, px, py);
    g_meta[p * 3 + 2] = make_float4(pz, (float)sam[p], mask[p] ? 1.f : 0.f, 0.f);
}

// ---------------- pairwise elementwise math ----------------
__device__ __forceinline__ void ew_loss(float fsl, float s, float tau, float enf,
                                        float& ap, float& am) {
    float th = tanh_approx(2.5f * (s - tau));
    float gp = fmaf(0.5f, th, 0.5f);
    float e1 = ex2_approx(fsl * gp);
    ap += e1;
    am += e1 * enf;
}

__device__ __forceinline__ void pair_ew(float fs,
    const float4& ra, const float4& rb, const float4& rc,
    const float4& ca, const float4& cb, const float4& cc,
    float* acc) {
    float mm = rc.z * cc.z;  // mask outer product
    float sflow = (ra.x * ca.x + ra.y * ca.y + ra.z * ca.z) * mm;
    float dx = ra.w - ca.w, dy = rb.x - cb.x, dz = rb.y - cb.y;
    float scol = (1.f - sqrt_approx(dx * dx + dy * dy + dz * dz) * 0.5773502691896258f) * mm;
    float qx = rb.z - cb.z, qy = rb.w - cb.w, qz = rc.x - cc.x;
    float sprox = ex2_approx(sqrt_approx(qx * qx + qy * qy + qz * qz) * (-50.f * L2E)) * mm;

    float fsl = fs * L2E;
    float enf = ex2_approx(-fsl);        // exp(-fs)
    float ef  = rcp_approx(enf);         // exp(+fs)
    ew_loss(fsl, sflow, 0.8f, enf, acc[0], acc[1]);
    ew_loss(fsl, scol,  0.7f, enf, acc[2], acc[3]);
    ew_loss(fsl, sprox, 0.5f, enf, acc[4], acc[5]);
    acc[6] += ef;
    if (rc.y == cc.y) {
        acc[7] += ef;
        acc[8] += 1.f;
    }
}

// ---------------- kernel 2: main N^2 pair loop (4x4 register blocking, FFMA2) --
// grid (Nc/64, Bc, NSLAB), block 256. Block tile: 64 rows x 128 cols (2 col-tiles).
// Thread (tx,ty): rows {ty+16i} x cols {tx+16j}, i,j in 0..3.
#define SSTR 68   // padded smem row stride (floats)

__global__ void __launch_bounds__(256, 2) k_pairs() {
    int b = blockIdx.y, rt = blockIdx.x, slab = blockIdx.z;
    int tid = threadIdx.x, tx = tid & 15, ty = tid >> 4;
    __shared__ float sA[64 * SSTR];
    __shared__ float sB[64 * SSTR];
    __shared__ float4 sMA[192];
    __shared__ float4 sMB[192];

    int rowbase = b * Nc + rt * 64;
    {
        const float4* src = (const float4*)(g_nf + (size_t)rowbase * Dc);
#pragma unroll
        for (int j = tid; j < 1024; j += 256) {
            float4 v = src[j];
            ((float4*)(sA + (j >> 4) * SSTR))[j & 15] = v;
        }
        if (tid < 192) sMA[tid] = ((const float4*)&g_meta[(size_t)rowbase * 3])[tid];
    }

    float acc[4][9];
#pragma unroll
    for (int i = 0; i < 4; i++)
#pragma unroll
        for (int j = 0; j < 9; j++) acc[i][j] = 0.f;

    int colslab = b * Nc + slab * CPS;
    for (int ctile = 0; ctile < CPS / 64; ctile++) {
        __syncthreads();
        int colbase = colslab + ctile * 64;
        {
            const float4* src = (const float4*)(g_nf + (size_t)colbase * Dc);
#pragma unroll
            for (int j = tid; j < 1024; j += 256) {
                float4 v = src[j];
                ((float4*)(sB + (j >> 4) * SSTR))[j & 15] = v;
            }
            if (tid < 192) sMB[tid] = ((const float4*)&g_meta[(size_t)colbase * 3])[tid];
        }
        __syncthreads();

        unsigned long long D[4][4];
#pragma unroll
        for (int i = 0; i < 4; i++)
#pragma unroll
            for (int j = 0; j < 4; j++) D[i][j] = 0ull;

#pragma unroll
        for (int kc = 0; kc < 16; kc++) {
            unsigned long long alo[4], ahi[4], blo[4], bhi[4];
#pragma unroll
            for (int i = 0; i < 4; i++) {
                float4 av = ((const float4*)(sA + (ty + 16 * i) * SSTR))[kc];
                alo[i] = pk(av.x, av.y); ahi[i] = pk(av.z, av.w);
            }
#pragma unroll
            for (int j = 0; j < 4; j++) {
                float4 bv = ((const float4*)(sB + (tx + 16 * j) * SSTR))[kc];
                blo[j] = pk(bv.x, bv.y); bhi[j] = pk(bv.z, bv.w);
            }
#pragma unroll
            for (int i = 0; i < 4; i++)
#pragma unroll
                for (int j = 0; j < 4; j++) {
                    fma2(D[i][j], alo[i], blo[j]);
                    fma2(D[i][j], ahi[i], bhi[j]);
                }
        }

#pragma unroll
        for (int i = 0; i < 4; i++) {
            int r = ty + 16 * i;
            float4 ra = sMA[r * 3 + 0], rb = sMA[r * 3 + 1], rc = sMA[r * 3 + 2];
#pragma unroll
            for (int j = 0; j < 4; j++) {
                int c = tx + 16 * j;
                float2 dv = upk(D[i][j]);
                float d = dv.x + dv.y;
                pair_ew(d, ra, rb, rc, sMB[c * 3 + 0], sMB[c * 3 + 1], sMB[c * 3 + 2],
                        acc[i]);
            }
        }
    }

    // reduce each row's partials across the 16 tx lanes
    float* slabbase = g_accp + (size_t)slab * Bc * Nc * 9;
#pragma unroll
    for (int i = 0; i < 4; i++) {
#pragma unroll
        for (int j = 0; j < 9; j++) {
            float v = acc[i][j];
#pragma unroll
            for (int o = 8; o >= 1; o >>= 1)
                v += __shfl_xor_sync(0xffffffffu, v, o);
            if (tx == 0)
                slabbase[(size_t)(rowbase + ty + 16 * i) * 9 + j] = v;
        }
    }
}

// ---------------- kernel 3: SAM pass + per-row loss finalize (warp per row) ----
__global__ void __launch_bounds__(256) k_sam(const int* __restrict__ sam) {
    int wl = threadIdx.x >> 5, lane = threadIdx.x & 31;
    int gw = blockIdx.x * 8 + wl;                 // global row id; 8 rows/block, same batch
    int b = (blockIdx.x * 8) >> 11;
    __shared__ int slabels[Nc];
    __shared__ float4 sf[8][16];
    __shared__ float4 srow[8];
    const int* samb = sam + b * Nc;
    for (int i = threadIdx.x; i < Nc; i += 256) slabels[i] = samb[i];
    if (lane < 16) sf[wl][lane] = ((const float4*)(g_nf + (size_t)gw * Dc))[lane];
    __syncthreads();

    float aj = 0.f;
    if (lane < 9) {
#pragma unroll
        for (int s = 0; s < NSLAB; s++)
            aj += g_accp[((size_t)s * Bc * Nc + gw) * 9 + lane];
    }
    float a0 = __shfl_sync(0xffffffffu, aj, 0);
    float a1 = __shfl_sync(0xffffffffu, aj, 1);
    float a2 = __shfl_sync(0xffffffffu, aj, 2);
    float a3 = __shfl_sync(0xffffffffu, aj, 3);
    float a4 = __shfl_sync(0xffffffffu, aj, 4);
    float a5 = __shfl_sync(0xffffffffu, aj, 5);
    float Sall = __shfl_sync(0xffffffffu, aj, 6);
    float Spos = __shfl_sync(0xffffffffu, aj, 7);
    float P    = __shfl_sync(0xffffffffu, aj, 8);
    float Sneg = Sall - Spos;

    int lbl = slabels[gw - b * Nc];
    float acc = 0.f;
    for (int m = lane; m < Nc; m += 32) {
        if (slabels[m] == lbl) {
            const float4* fm = (const float4*)(g_nf + (size_t)(b * Nc + m) * Dc);
            float fs = 0.f;
#pragma unroll
            for (int k = 0; k < 16; k++) {
                float4 x = sf[wl][k]; float4 y = fm[k];
                fs += x.x * y.x + x.y * y.y + x.z * y.z + x.w * y.w;
            }
            acc += __logf(__expf(fs) + Sneg) - fs;
        }
    }
#pragma unroll
    for (int o = 16; o >= 1; o >>= 1) acc += __shfl_xor_sync(0xffffffffu, acc, o);

    if (lane == 0) {
        float m = g_meta[(size_t)gw * 3 + 2].z;
        float wloss = m * (log1pf(a0) + log1pf(a1) + log1pf(a2) +
                           log1pf(a3) + log1pf(a4) + log1pf(a5));
        float valid = P > 0.f ? 1.f : 0.f;
        float nll = acc / fmaxf(P, 1e-6f);
        srow[wl] = make_float4(wloss, m, nll * valid, valid);
    }
    __syncthreads();
    if (threadIdx.x == 0) {
        float4 s = srow[0];
#pragma unroll
        for (int j = 1; j < 8; j++) {
            float4 v = srow[j];
            s.x += v.x; s.y += v.y; s.z += v.z; s.w += v.w;
        }
        g_blockloss[blockIdx.x] = s;
    }
}

// ---------------- kernel 4: tiny final reduction (1024 entries) ----------------
__global__ void __launch_bounds__(1024) k_final(float* __restrict__ out) {
    int tid = threadIdx.x;
    float4 v = g_blockloss[tid];
    float s0 = v.x, s1 = v.y, s2 = v.z, s3 = v.w;
#pragma unroll
    for (int o = 16; o >= 1; o >>= 1) {
        s0 += __shfl_xor_sync(0xffffffffu, s0, o);
        s1 += __shfl_xor_sync(0xffffffffu, s1, o);
        s2 += __shfl_xor_sync(0xffffffffu, s2, o);
        s3 += __shfl_xor_sync(0xffffffffu, s3, o);
    }
    __shared__ float4 wred[32];
    int w = tid >> 5, lane = tid & 31;
    if (lane == 0) wred[w] = make_float4(s0, s1, s2, s3);
    __syncthreads();
    if (tid == 0) {
        float tot = 0.f;
        for (int bb = 0; bb < Bc; bb++) {
            float p0 = 0.f, p1 = 0.f, p2 = 0.f, p3 = 0.f;
            for (int ww = bb * 8; ww < bb * 8 + 8; ww++) {
                float4 t = wred[ww];
                p0 += t.x; p1 += t.y; p2 += t.z; p3 += t.w;
            }
            tot += -p0 / p1 + p2 / fmaxf(p3, 1e-6f);
        }
        out[0] = tot * (1.f / Bc);
    }
}

// ---------------- launcher ----------------
extern "C" void kernel_launch(void* const* d_in, const int* in_sizes, int n_in,
                              void* d_out, int out_size) {
    const float* feat         = (const float*)d_in[0];
    const float* flow         = (const float*)d_in[1];
    const float* pts          = (const float*)d_in[2];
    const int* colors         = (const int*)d_in[3];
    const int* sam            = (const int*)d_in[4];
    const unsigned char* mask = (const unsigned char*)d_in[5];

    k_prep<<<(Bc * Nc + 127) / 128, 128>>>(feat, flow, pts, colors, sam, mask);
    dim3 grid(Nc / 64, Bc, NSLAB);
    k_pairs<<<grid, 256>>>();
    k_sam<<<Bc * Nc / 8, 256>>>(sam);
    k_final<<<1, 1024>>>((float*)d_out);
}